// round 14
// baseline (speedup 1.0000x reference)
#include <cuda_runtime.h>
#include <cuda_bf16.h>
#include <math.h>
#include <stdint.h>

#define BB   4
#define L1C  1024
#define L2C  512
#define LT   1536
#define DPG  2304
#define DEX  1024
#define NH   8
#define NKV  4
#define DHD  256
#define QK_SCALE 0.0625f

#define PERM8(j) ((((j) & 3) << 1) | ((j) >> 2))

// ---------------- scratch (device globals) -----------------------------------
__device__ float g_Q[(size_t)BB * LT * NH * DHD];
__device__ float g_K[(size_t)BB * LT * NKV * DHD];
__device__ float g_V[(size_t)BB * LT * NKV * DHD];

__device__ uint32_t g_Qh[(size_t)BB * LT * NH * 128];
__device__ uint32_t g_Ql[(size_t)BB * LT * NH * 128];
__device__ uint32_t g_Kh[(size_t)BB * LT * NKV * 128];
__device__ uint32_t g_Kl[(size_t)BB * LT * NKV * 128];

__device__ uint32_t g_VTh[(size_t)BB * NKV * DHD * (LT / 2)];
__device__ uint32_t g_VTl[(size_t)BB * NKV * DHD * (LT / 2)];

__device__ uint32_t g_ahi[(size_t)BB * LT * NH * 128];
__device__ uint32_t g_alo[(size_t)BB * LT * NH * 128];

#define OP_PG   0u
#define OP_EX   4718592u
#define OP_WQ0  5767168u
#define OP_WK0  8126464u
#define OP_WV0  9306112u
#define OP_WO0  10485760u
#define OP_WQ1  12845056u
#define OP_WK1  13893632u
#define OP_WV1  14417920u
#define OP_WO1  14942208u
#define OP_TOT  15990784u
__device__ uint32_t g_hi[OP_TOT];
__device__ uint32_t g_lo[OP_TOT];

// ---------------- helpers ----------------------------------------------------
__device__ __forceinline__ uint32_t pack_bf(float a, float b)
{
    __nv_bfloat162 t = __floats2bfloat162_rn(a, b);
    return *(uint32_t*)&t;
}
__device__ __forceinline__ void cpa16(uint32_t dst, const void* src)
{
    asm volatile("cp.async.cg.shared.global [%0], [%1], 16;" :: "r"(dst), "l"(src));
}

#define MMA_BF16(d, a, b)                                                     \
    asm volatile("mma.sync.aligned.m16n8k16.row.col.f32.bf16.bf16.f32 "       \
                 "{%0,%1,%2,%3}, {%4,%5,%6,%7}, {%8,%9}, {%0,%1,%2,%3};"      \
                 : "+f"(d[0]), "+f"(d[1]), "+f"(d[2]), "+f"(d[3])             \
                 : "r"(a[0]), "r"(a[1]), "r"(a[2]), "r"(a[3]),                \
                   "r"(b[0]), "r"(b[1]))

// ---------------- fused bf16-split conversion --------------------------------
struct CvtArgs {
    const float* src[10];
    uint32_t off[10];
    int n16[10];
};

__global__ void cvt_bsplit(CvtArgs a)
{
    const int e = blockIdx.y;
    const int i = blockIdx.x * blockDim.x + threadIdx.x;
    if (i >= a.n16[e]) return;
    const float4* s = (const float4*)(a.src[e]) + (size_t)i * 4;
    uint32_t* hb = g_hi + a.off[e] + (size_t)i * 8;
    uint32_t* lb = g_lo + a.off[e] + (size_t)i * 8;
    float v[16];
#pragma unroll
    for (int q = 0; q < 4; q++) {
        float4 f = s[q];
        v[q * 4 + 0] = f.x; v[q * 4 + 1] = f.y; v[q * 4 + 2] = f.z; v[q * 4 + 3] = f.w;
    }
#pragma unroll
    for (int j = 0; j < 8; j++) {
        const float x0 = v[2 * j], x1 = v[2 * j + 1];
        const float h0 = __bfloat162float(__float2bfloat16_rn(x0));
        const float h1 = __bfloat162float(__float2bfloat16_rn(x1));
        const int p = PERM8(j);
        hb[p] = pack_bf(h0, h1);
        lb[p] = pack_bf(x0 - h0, x1 - h1);
    }
}

// ---------------- bf16x3 NT GEMM: 4 warps, 64x64 warp tile -------------------
#define CH 16
#define PLN (128 * CH)
#define STG (4 * PLN)
#define GSM_BYTES (3 * STG * 4)

struct GemmJob {
    const uint32_t *Ah, *Al, *Wh, *Wl;
    int K2;
    int a_rpb, a_bs, a_off;
    int c_rpb, c_bs, c_off;
    int n1, n2;
    float *C0, *C1, *C2;
    int ldc0, ldc1, ldc2;
    int gx, gy;
};

__global__ __launch_bounds__(128, 2) void gemm_b3(GemmJob j0, GemmJob j1)
{
    const GemmJob J = blockIdx.z ? j1 : j0;
    if ((int)blockIdx.x >= J.gx || (int)blockIdx.y >= J.gy) return;

    extern __shared__ uint32_t smg[];
    const int tid = threadIdx.x;
    const int wid = tid >> 5, lane = tid & 31;
    const int warp_m = wid >> 1, warp_n = wid & 1;
    const int bm = blockIdx.y * 128, bn = blockIdx.x * 128;
    const int K2 = J.K2;

    const int p  = tid >> 5;
    const int tr = tid & 31;
    const uint32_t* pb = (p == 0) ? J.Ah : (p == 1) ? J.Al : (p == 2) ? J.Wh : J.Wl;
    const uint32_t sbase = (uint32_t)__cvta_generic_to_shared(smg);
    const uint32_t* srow[4];
    uint32_t dbase[4];
    int rsw[4];
#pragma unroll
    for (int i = 0; i < 4; i++) {
        const int r = tr * 4 + i;
        int g;
        if (p < 2) {
            const int m = bm + r;
            g = (m / J.a_rpb) * J.a_bs + J.a_off + (m % J.a_rpb);
        } else g = bn + r;
        srow[i] = pb + (size_t)g * K2;
        dbase[i] = sbase + (p * PLN + r * CH) * 4;
        rsw[i]  = (r & 2) << 1;
    }

    float acc[4][8][4];
#pragma unroll
    for (int i = 0; i < 4; i++)
#pragma unroll
        for (int j = 0; j < 8; j++)
#pragma unroll
            for (int r = 0; r < 4; r++) acc[i][j][r] = 0.f;

    const int nk = K2 >> 4;

#define G_ISSUE(kc)                                                           \
    do {                                                                      \
        const int _ko = (kc) * CH;                                            \
        const uint32_t _sb = ((kc) % 3) * STG * 4;                            \
        _Pragma("unroll")                                                     \
        for (int i = 0; i < 4; i++) {                                         \
            _Pragma("unroll")                                                 \
            for (int j = 0; j < 4; j++)                                       \
                cpa16(dbase[i] + _sb + (((2 * j) ^ rsw[i]) * 2) * 4,          \
                      srow[i] + _ko + j * 4);                                 \
        }                                                                     \
        asm volatile("cp.async.commit_group;");                               \
    } while (0)

    G_ISSUE(0);
    G_ISSUE(1);

    const int lr = lane >> 2, lc = lane & 3;
    const int fsw = (lr & 2) << 1;

    for (int kc = 0; kc < nk; kc++) {
        if (kc + 2 < nk) { asm volatile("cp.async.wait_group 1;"); }
        else             { asm volatile("cp.async.wait_group 0;"); }
        __syncthreads();
        if (kc + 2 < nk) G_ISSUE(kc + 2);

        const uint32_t* st = smg + (kc % 3) * STG;
        const uint32_t* ah_p = st + 0 * PLN + (warp_m * 64 + lr) * CH;
        const uint32_t* al_p = st + 1 * PLN + (warp_m * 64 + lr) * CH;
        const uint32_t* wh_p = st + 2 * PLN + (warp_n * 64 + lr) * CH;
        const uint32_t* wl_p = st + 3 * PLN + (warp_n * 64 + lr) * CH;

#pragma unroll
        for (int g = 0; g < 2; g++) {
            const int q2 = ((g * 4 + lc) ^ fsw) * 2;
            uint32_t ah[4][4], bh[8][2];
            uint2 t;
#pragma unroll
            for (int mf = 0; mf < 4; mf++) {
                t = *(const uint2*)(ah_p + mf * 16 * CH + q2);            ah[mf][0] = t.x; ah[mf][2] = t.y;
                t = *(const uint2*)(ah_p + mf * 16 * CH + 8 * CH + q2);   ah[mf][1] = t.x; ah[mf][3] = t.y;
            }
#pragma unroll
            for (int nf = 0; nf < 8; nf++) {
                t = *(const uint2*)(wh_p + nf * 8 * CH + q2);  bh[nf][0] = t.x; bh[nf][1] = t.y;
            }
#pragma unroll
            for (int nf = 0; nf < 8; nf++)
#pragma unroll
                for (int mf = 0; mf < 4; mf++)
                    MMA_BF16(acc[mf][nf], ah[mf], bh[nf]);
#pragma unroll
            for (int mf = 0; mf < 4; mf++) {
                uint32_t al[4];
                t = *(const uint2*)(al_p + mf * 16 * CH + q2);            al[0] = t.x; al[2] = t.y;
                t = *(const uint2*)(al_p + mf * 16 * CH + 8 * CH + q2);   al[1] = t.x; al[3] = t.y;
#pragma unroll
                for (int nf = 0; nf < 8; nf++)
                    MMA_BF16(acc[mf][nf], al, bh[nf]);
            }
#pragma unroll
            for (int nf = 0; nf < 8; nf++) {
                uint32_t bl[2];
                t = *(const uint2*)(wl_p + nf * 8 * CH + q2);  bl[0] = t.x; bl[1] = t.y;
#pragma unroll
                for (int mf = 0; mf < 4; mf++)
                    MMA_BF16(acc[mf][nf], ah[mf], bl);
            }
        }
    }
#undef G_ISSUE

    float* Cb; int ldc, coff;
    if (bn < J.n1)      { Cb = J.C0; ldc = J.ldc0; coff = 0;    }
    else if (bn < J.n2) { Cb = J.C1; ldc = J.ldc1; coff = J.n1; }
    else                { Cb = J.C2; ldc = J.ldc2; coff = J.n2; }

#pragma unroll
    for (int mf = 0; mf < 4; mf++) {
        const int m0 = bm + warp_m * 64 + mf * 16 + lr;
        const int m1 = m0 + 8;
        const int cr0 = (m0 / J.c_rpb) * J.c_bs + J.c_off + (m0 % J.c_rpb);
        const int cr1 = (m1 / J.c_rpb) * J.c_bs + J.c_off + (m1 % J.c_rpb);
#pragma unroll
        for (int nf = 0; nf < 8; nf++) {
            const int col = bn - coff + warp_n * 64 + nf * 8 + lc * 2;
            *(float2*)&Cb[(size_t)cr0 * ldc + col] = make_float2(acc[mf][nf][0], acc[mf][nf][1]);
            *(float2*)&Cb[(size_t)cr1 * ldc + col] = make_float2(acc[mf][nf][2], acc[mf][nf][3]);
        }
    }
}

// ---------------- RoPE + bf16 split + pack (Q and K fused) -------------------
__global__ void rope_pack2(const float* __restrict__ Xq, const float* __restrict__ Xk,
                           const float* __restrict__ cs, const float* __restrict__ sn,
                           uint32_t* __restrict__ qh_, uint32_t* __restrict__ ql_,
                           uint32_t* __restrict__ kh_, uint32_t* __restrict__ kl_)
{
    const int hh = blockIdx.x;
    const int l = blockIdx.y;
    const int b = blockIdx.z;
    const int j = threadIdx.x;
    const int isQ = hh < NH;
    const int h = isQ ? hh : hh - NH;
    const int nheads = isQ ? NH : NKV;
    const float scale = isQ ? QK_SCALE : 1.0f;
    const float* X = isQ ? Xq : Xk;
    uint32_t* oh = isQ ? qh_ : kh_;
    uint32_t* ol = isQ ? ql_ : kl_;

    const size_t row = (size_t)b * LT + l;
    const float2 c2 = *(const float2*)&cs[row * 128 + 2 * j];
    const float2 s2 = *(const float2*)&sn[row * 128 + 2 * j];
    const size_t base = (row * nheads + h) * DHD;
    const float2 xa = *(const float2*)&X[base + 2 * j];
    const float2 xb = *(const float2*)&X[base + 128 + 2 * j];
    const float y1a = (xa.x * c2.x - xb.x * s2.x) * scale;
    const float y1b = (xa.y * c2.y - xb.y * s2.y) * scale;
    const float y2a = (xb.x * c2.x + xa.x * s2.x) * scale;
    const float y2b = (xb.y * c2.y + xa.y * s2.y) * scale;

    const size_t ob = (row * nheads + h) * 128;
    const int p1 = (j & ~7) | PERM8(j & 7);
    const int p2 = 64 + p1;
    const float h1a = __bfloat162float(__float2bfloat16_rn(y1a));
    const float h1b = __bfloat162float(__float2bfloat16_rn(y1b));
    const float h2a = __bfloat162float(__float2bfloat16_rn(y2a));
    const float h2b = __bfloat162float(__float2bfloat16_rn(y2b));
    oh[ob + p1] = pack_bf(h1a, h1b);
    ol[ob + p1] = pack_bf(y1a - h1a, y1b - h1b);
    oh[ob + p2] = pack_bf(h2a, h2b);
    ol[ob + p2] = pack_bf(y2a - h2a, y2b - h2b);
}

// ---------------- V transpose + bf16 split (coalesced writes) ----------------
__global__ __launch_bounds__(256) void vt_pack()
{
    __shared__ float t[64][65];
    const int b   = blockIdx.z >> 2;
    const int hkv = blockIdx.z & 3;
    const int l0 = blockIdx.x * 64;
    const int d0 = blockIdx.y * 64;
    const int tid = threadIdx.x;

    for (int i = tid; i < 64 * 64; i += 256) {
        const int lrow = i >> 6, dcol = i & 63;
        t[lrow][dcol] = g_V[(((size_t)b * LT + l0 + lrow) * NKV + hkv) * DHD + d0 + dcol];
    }
    __syncthreads();

    const int drow = tid >> 2;
    const int mg = tid & 3;
    const size_t obase = (((size_t)b * NKV + hkv) * DHD + d0 + drow) * (LT / 2) + l0 / 2;
#pragma unroll
    for (int m = 0; m < 8; m++) {
        const int lp = mg * 8 + m;
        const float v0 = t[2 * lp][drow];
        const float v1 = t[2 * lp + 1][drow];
        const float h0 = __bfloat162float(__float2bfloat16_rn(v0));
        const float h1 = __bfloat162float(__float2bfloat16_rn(v1));
        const int pos = mg * 8 + PERM8(m);
        g_VTh[obase + pos] = pack_bf(h0, h1);
        g_VTl[obase + pos] = pack_bf(v0 - h0, v1 - h1);
    }
}

// ---------------- bf16x3 flash attention, 256 threads, kd-split QK -----------
// smem u32 offsets
#define AQH 0
#define AQL 8192
#define AKH 16384
#define AKL 24576
#define AVH 32768
#define AVL 40960
#define AS0 49152
#define AS1 53504
#define AAS 57856
#define ALS 57920
#define SMEM_ATTN (57984 * 4)

__global__ __launch_bounds__(256, 1) void attn_mma(const float* __restrict__ mask)
{
    extern __shared__ uint32_t su[];
    float* S0  = (float*)(su + AS0);   // [64][68] fp32 partial (kd=0, +mask)
    float* S1f = (float*)(su + AS1);   // [64][68] fp32 partial (kd=1); P aliases here
    float* Asc = (float*)(su + AAS);
    float* Lsc = (float*)(su + ALS);

    const int tid = threadIdx.x;
    const int qt = blockIdx.x;
    const int h  = blockIdx.y;
    const int b  = blockIdx.z;
    const int hkv = h >> 1;
    const int wid = tid >> 5, lane = tid & 31;
    const int wq = wid & 1, wk = (wid >> 1) & 1, kd = wid >> 2;  // QK roles
    const int wd = wid >> 1;                                     // PV role 0..3
    const int lr = lane >> 2, lc = lane & 3;
    const int fsw = (lr & 3) << 2;
    const int srow = tid >> 2, part = tid & 3;

    const uint32_t sb = (uint32_t)__cvta_generic_to_shared(su);

    // ---- prologue: Q + K(0) (group 0), V(0) (group 1) ----
    {
        const uint32_t* qsrc[2] = { g_Qh, g_Ql };
        const uint32_t* ksrc[2] = { g_Kh, g_Kl };
#pragma unroll
        for (int pl = 0; pl < 2; pl++) {
            for (int i = tid; i < 2048; i += 256) {
                const int row = i >> 5, ch = i & 31;
                const uint32_t dst = sb + ((pl ? AQL : AQH) + row * 128 +
                                           (((2 * ch) ^ ((row & 3) << 2)) * 2)) * 4;
                cpa16(dst, qsrc[pl] + (((size_t)b * LT + qt * 64 + row) * NH + h) * 128 + ch * 4);
            }
            for (int i = tid; i < 2048; i += 256) {
                const int row = i >> 5, ch = i & 31;
                const uint32_t dst = sb + ((pl ? AKL : AKH) + row * 128 +
                                           (((2 * ch) ^ ((row & 3) << 2)) * 2)) * 4;
                cpa16(dst, ksrc[pl] + (((size_t)b * LT + row) * NKV + hkv) * 128 + ch * 4);
            }
        }
        asm volatile("cp.async.commit_group;");
        const uint32_t* vsrc[2] = { g_VTh, g_VTl };
#pragma unroll
        for (int pl = 0; pl < 2; pl++)
            for (int i = tid; i < 2048; i += 256) {
                const int row = i >> 3, ch = i & 7;
                const uint32_t dst = sb + ((pl ? AVL : AVH) + row * 32 +
                                           (((2 * ch) ^ ((row & 3) << 2)) * 2)) * 4;
                cpa16(dst, vsrc[pl] + (((size_t)b * NKV + hkv) * DHD + row) * (LT / 2) + ch * 4);
            }
        asm volatile("cp.async.commit_group;");
    }

    float accO[16][4];   // [mf*8+nf][4], PV tile 32q x 64d
#pragma unroll
    for (int i = 0; i < 16; i++)
#pragma unroll
        for (int j = 0; j < 4; j++) accO[i][j] = 0.f;
    float m_run = -1e30f, l_run = 0.f;

    for (int kt = 0; kt < LT / 64; kt++) {
        asm volatile("cp.async.wait_group 1;");
        __syncthreads();

        // ---- mask prefetch (kd==0 warps only) ----
        float2 mk0[2][2], mk1[2][2];
        if (kd == 0) {
#pragma unroll
            for (int mf = 0; mf < 2; mf++) {
                const size_t mr = ((size_t)b * LT + qt * 64 + wq * 32 + mf * 16 + lr) * LT
                                  + kt * 64 + wk * 32;
#pragma unroll
                for (int nf = 0; nf < 2; nf++) {
                    mk0[mf][nf] = *(const float2*)&mask[mr + nf * 16 + lc * 2];
                    mk1[mf][nf] = *(const float2*)&mask[mr + 8 * LT + nf * 16 + lc * 2];
                }
            }
        }

        // ---- QK: warp tile 32x32, d-half kd (8 groups) ----
        float accS[2][4][4];
#pragma unroll
        for (int mf = 0; mf < 2; mf++)
#pragma unroll
            for (int nf = 0; nf < 4; nf++)
#pragma unroll
                for (int r = 0; r < 4; r++) accS[mf][nf][r] = 0.f;
        {
            const uint32_t* qhb = su + AQH + (wq * 32 + lr) * 128;
            const uint32_t* qlb = su + AQL + (wq * 32 + lr) * 128;
            const uint32_t* khb = su + AKH + (wk * 32 + lr) * 128;
            const uint32_t* klb = su + AKL + (wk * 32 + lr) * 128;
#pragma unroll 2
            for (int g = 0; g < 8; g++) {
                const int q2 = kd * 64 + (((g * 4 + lc) ^ fsw) * 2);
                uint32_t ah[2][4], bh[4][2];
                uint2 t;
#pragma unroll
                for (int mf = 0; mf < 2; mf++) {
                    t = *(const uint2*)(qhb + mf * 16 * 128 + q2);            ah[mf][0] = t.x; ah[mf][2] = t.y;
                    t = *(const uint2*)(qhb + mf * 16 * 128 + 8 * 128 + q2);  ah[mf][1] = t.x; ah[mf][3] = t.y;
                }
#pragma unroll
                for (int nf = 0; nf < 4; nf++) {
                    t = *(const uint2*)(khb + nf * 8 * 128 + q2);  bh[nf][0] = t.x; bh[nf][1] = t.y;
                }
#pragma unroll
                for (int nf = 0; nf < 4; nf++)
#pragma unroll
                    for (int mf = 0; mf < 2; mf++)
                        MMA_BF16(accS[mf][nf], ah[mf], bh[nf]);
#pragma unroll
                for (int mf = 0; mf < 2; mf++) {
                    uint32_t al[4];
                    t = *(const uint2*)(qlb + mf * 16 * 128 + q2);            al[0] = t.x; al[2] = t.y;
                    t = *(const uint2*)(qlb + mf * 16 * 128 + 8 * 128 + q2);  al[1] = t.x; al[3] = t.y;
#pragma unroll
                    for (int nf = 0; nf < 4; nf++)
                        MMA_BF16(accS[mf][nf], al, bh[nf]);
                }
#pragma unroll
                for (int nf = 0; nf < 4; nf++) {
                    uint32_t bl[2];
                    t = *(const uint2*)(klb + nf * 8 * 128 + q2);  bl[0] = t.x; bl[1] = t.y;
#pragma unroll
                    for (int mf = 0; mf < 2; mf++)
                        MMA_BF16(accS[mf][nf], ah[mf], bl);
                }
            }
        }
        // ---- write S partial (kd=0 adds mask) ----
        {
            float* Sb = kd ? S1f : S0;
#pragma unroll
            for (int mf = 0; mf < 2; mf++) {
                const int r0 = wq * 32 + mf * 16 + lr;
#pragma unroll
                for (int nf = 0; nf < 4; nf++) {
                    const int col = wk * 32 + nf * 8 + lc * 2;
                    float v0 = accS[mf][nf][0], v1 = accS[mf][nf][1];
                    float v2 = accS[mf][nf][2], v3 = accS[mf][nf][3];
                    if (kd == 0) {
                        const float2 a0 = mk0[mf][nf >> 1];
                        const float2 a1 = mk1[mf][nf >> 1];
                        // nf pairs share float2? no: mask loaded per nf*16 -> need per-nf
                    }
                    // mask add handled below
                    *(float2*)&Sb[r0 * 68 + col] = make_float2(v0, v1);
                    *(float2*)&Sb[(r0 + 8) * 68 + col] = make_float2(v2, v3);
                }
            }
            // add mask into S0 (kd==0): direct indexed add, values already in regs
            if (kd == 0) {
#pragma unroll
                for (int mf = 0; mf < 2; mf++) {
                    const int r0 = wq * 32 + mf * 16 + lr;
#pragma unroll
                    for (int nf = 0; nf < 4; nf++) {
                        const int col = wk * 32 + nf * 8 + lc * 2;
                        const float2 m0 = (nf < 2) ? ((nf & 1) ? mk0[mf][0] : mk0[mf][0]) : mk0[mf][1];
                        const float2 m1 = (nf < 2) ? mk1[mf][0] : mk1[mf][1];
                        // NOTE: mask prefetch granularity is 16 cols (2 nf per float2 slot is wrong);
                        // reload directly to stay correct:
                        const size_t mr = ((size_t)b * LT + qt * 64 + r0) * LT + kt * 64 + col;
                        const float2 q0 = *(const float2*)&mask[mr];
                        const float2 q1 = *(const float2*)&mask[mr + 8 * LT];
                        float2 s0 = *(float2*)&S0[r0 * 68 + col];
                        float2 s1 = *(float2*)&S0[(r0 + 8) * 68 + col];
                        *(float2*)&S0[r0 * 68 + col] = make_float2(s0.x + q0.x, s0.y + q0.y);
                        *(float2*)&S0[(r0 + 8) * 68 + col] = make_float2(s1.x + q1.x, s1.y + q1.y);
                        (void)m0; (void)m1;
                    }
                }
            }
        }
        __syncthreads();

        if (kt + 1 < LT / 64) {
            const uint32_t* ksrc[2] = { g_Kh, g_Kl };
#pragma unroll
            for (int pl = 0; pl < 2; pl++)
                for (int i = tid; i < 2048; i += 256) {
                    const int row = i >> 5, ch = i & 31;
                    const uint32_t dst = sb + ((pl ? AKL : AKH) + row * 128 +
                                               (((2 * ch) ^ ((row & 3) << 2)) * 2)) * 4;
                    cpa16(dst, ksrc[pl] + (((size_t)b * LT + (kt + 1) * 64 + row) * NKV + hkv) * 128 + ch * 4);
                }
            asm volatile("cp.async.commit_group;");
        }

        // ---- softmax (4 threads/row, 16 cols each); P -> S1 rows ----
        {
            const int rb = srow * 68 + part * 16;
            float pv[16];
            float lm = -1e30f;
#pragma unroll
            for (int j = 0; j < 16; j++) {
                pv[j] = S0[rb + j] + S1f[rb + j];
                lm = fmaxf(lm, pv[j]);
            }
            lm = fmaxf(lm, __shfl_xor_sync(0xffffffffu, lm, 1));
            lm = fmaxf(lm, __shfl_xor_sync(0xffffffffu, lm, 2));
            const float mnew = fmaxf(m_run, lm);
            const float alpha = __expf(m_run - mnew);
            float ls = 0.f;
#pragma unroll
            for (int j = 0; j < 16; j++) { pv[j] = __expf(pv[j] - mnew); ls += pv[j]; }
            ls += __shfl_xor_sync(0xffffffffu, ls, 1);
            ls += __shfl_xor_sync(0xffffffffu, ls, 2);
            l_run = l_run * alpha + ls;
            m_run = mnew;
            if (part == 0) Asc[srow] = alpha;

            __syncwarp();   // all reads of this row's S1 done before P overwrites
            uint32_t* Pr = su + AS1 + srow * 68;   // hi [0..31], lo [32..63]
            const int swz = (srow & 3) << 2;
#pragma unroll
            for (int m = 0; m < 8; m++) {
                const float p0 = pv[2 * m], p1 = pv[2 * m + 1];
                const float h0 = __bfloat162float(__float2bfloat16_rn(p0));
                const float h1 = __bfloat162float(__float2bfloat16_rn(p1));
                const int pp = part * 8 + m;
                const int u = (pp & ~7) | PERM8(pp & 7);
                const int pos = (((u >> 1) ^ swz) * 2) + (u & 1);
                Pr[pos] = pack_bf(h0, h1);
                Pr[32 + pos] = pack_bf(p0 - h0, p1 - h1);
            }
        }
        if (kt + 1 < LT / 64) { asm volatile("cp.async.wait_group 1;"); }
        else                  { asm volatile("cp.async.wait_group 0;"); }
        __syncthreads();

        // ---- rescale O, O += P V : warp tile 32q x 64d over 64 keys ----
        {
            float a0[2], a1[2];
#pragma unroll
            for (int mf = 0; mf < 2; mf++) {
                a0[mf] = Asc[wq * 32 + mf * 16 + lr];
                a1[mf] = Asc[wq * 32 + mf * 16 + lr + 8];
            }
#pragma unroll
            for (int mf = 0; mf < 2; mf++)
#pragma unroll
                for (int nf = 0; nf < 8; nf++) {
                    accO[mf * 8 + nf][0] *= a0[mf]; accO[mf * 8 + nf][1] *= a0[mf];
                    accO[mf * 8 + nf][2] *= a1[mf]; accO[mf * 8 + nf][3] *= a1[mf];
                }
            const uint32_t* vhb = su + AVH + (wd * 64 + lr) * 32;
            const uint32_t* vlb = su + AVL + (wd * 64 + lr) * 32;
#pragma unroll
            for (int g = 0; g < 4; g++) {
                const int q2 = ((g * 4 + lc) ^ fsw) * 2;
                uint32_t ph[2][4], vh[8][2];
                uint2 t;
#pragma unroll
                for (int mf = 0; mf < 2; mf++) {
                    const uint32_t* pr = su + AS1 + (wq * 32 + mf * 16 + lr) * 68;
                    t = *(const uint2*)(pr + q2);            ph[mf][0] = t.x; ph[mf][2] = t.y;
                    t = *(const uint2*)(pr + 8 * 68 + q2);   ph[mf][1] = t.x; ph[mf][3] = t.y;
                }
#pragma unroll
                for (int nf = 0; nf < 8; nf++) {
                    t = *(const uint2*)(vhb + nf * 8 * 32 + q2);  vh[nf][0] = t.x; vh[nf][1] = t.y;
                }
#pragma unroll
                for (int nf = 0; nf < 8; nf++)
#pragma unroll
                    for (int mf = 0; mf < 2; mf++)
                        MMA_BF16(accO[mf * 8 + nf], ph[mf], vh[nf]);
#pragma unroll
                for (int mf = 0; mf < 2; mf++) {
                    const uint32_t* pr = su + AS1 + (wq * 32 + mf * 16 + lr) * 68 + 32;
                    uint32_t pl[4];
                    t = *(const uint2*)(pr + q2);            pl[0] = t.x; pl[2] = t.y;
                    t = *(const uint2*)(pr + 8 * 68 + q2);   pl[1] = t.x; pl[3] = t.y;
#pragma unroll
                    for (int nf = 0; nf < 8; nf++)
                        MMA_BF16(accO[mf * 8 + nf], pl, vh[nf]);
                }
#pragma unroll
                for (int nf = 0; nf < 8; nf++) {
                    uint32_t vl[2];
                    t = *(const uint2*)(vlb + nf * 8 * 32 + q2);  vl[0] = t.x; vl[1] = t.y;
#pragma unroll
                    for (int mf = 0; mf < 2; mf++)
                        MMA_BF16(accO[mf * 8 + nf], ph[mf], vl);
                }
            }
        }
        __syncthreads();

        if (kt + 1 < LT / 64) {
            const uint32_t* vsrc[2] = { g_VTh, g_VTl };
#pragma unroll
            for (int pl = 0; pl < 2; pl++)
                for (int i = tid; i < 2048; i += 256) {
                    const int row = i >> 3, ch = i & 7;
                    const uint32_t dst = sb + ((pl ? AVL : AVH) + row * 32 +
                                               (((2 * ch) ^ ((row & 3) << 2)) * 2)) * 4;
                    cpa16(dst, vsrc[pl] + (((size_t)b * NKV + hkv) * DHD + row) * (LT / 2) +
                               (kt + 1) * 32 + ch * 4);
                }
            asm volatile("cp.async.commit_group;");
        }
    }

    if (part == 0) Lsc[srow] = l_run;
    __syncthreads();

    // ---- epilogue ----
    {
#pragma unroll
        for (int mf = 0; mf < 2; mf++) {
            const float il0 = 1.f / Lsc[wq * 32 + mf * 16 + lr];
            const float il1 = 1.f / Lsc[wq * 32 + mf * 16 + lr + 8];
            const size_t r0 = (size_t)b * LT + qt * 64 + wq * 32 + mf * 16 + lr;
            const size_t r1 = r0 + 8;
#pragma unroll
            for (int nf = 0; nf < 8; nf++) {
                const int p = h * 128 + wd * 32 + nf * 4 + lc;
                const int pos = (p & ~7) | PERM8(p & 7);
                const float v0 = accO[mf * 8 + nf][0] * il0, v1 = accO[mf * 8 + nf][1] * il0;
                const float v2 = accO[mf * 8 + nf][2] * il1, v3 = accO[mf * 8 + nf][3] * il1;
                const float h0 = __bfloat162float(__float2bfloat16_rn(v0));
                const float h1 = __bfloat162float(__float2bfloat16_rn(v1));
                const float h2 = __bfloat162float(__float2bfloat16_rn(v2));
                const float h3 = __bfloat162float(__float2bfloat16_rn(v3));
                g_ahi[r0 * 1024 + pos] = pack_bf(h0, h1);
                g_alo[r0 * 1024 + pos] = pack_bf(v0 - h0, v1 - h1);
                g_ahi[r1 * 1024 + pos] = pack_bf(h2, h3);
                g_alo[r1 * 1024 + pos] = pack_bf(v2 - h2, v3 - h3);
            }
        }
    }
}

// ---------------- launch ----------------------------------------------------
extern "C" void kernel_launch(void* const* d_in, const int* in_sizes, int n_in,
                              void* d_out, int out_size)
{
    const float* pg   = (const float*)d_in[0];
    const float* ex   = (const float*)d_in[1];
    const float* cs   = (const float*)d_in[2];
    const float* sn   = (const float*)d_in[3];
    const float* mask = (const float*)d_in[4];
    const float* Wq0  = (const float*)d_in[5];
    const float* Wk0  = (const float*)d_in[6];
    const float* Wv0  = (const float*)d_in[7];
    const float* Wo0  = (const float*)d_in[8];
    const float* Wq1  = (const float*)d_in[9];
    const float* Wk1  = (const float*)d_in[10];
    const float* Wv1  = (const float*)d_in[11];
    const float* Wo1  = (const float*)d_in[12];
    float* out = (float*)d_out;

    float *Qd, *Kd, *Vd;
    uint32_t *Ahd, *Ald, *Hv, *Lv, *Qhp, *Qlp, *Khp, *Klp;
    cudaGetSymbolAddress((void**)&Qd, g_Q);
    cudaGetSymbolAddress((void**)&Kd, g_K);
    cudaGetSymbolAddress((void**)&Vd, g_V);
    cudaGetSymbolAddress((void**)&Ahd, g_ahi);
    cudaGetSymbolAddress((void**)&Ald, g_alo);
    cudaGetSymbolAddress((void**)&Hv, g_hi);
    cudaGetSymbolAddress((void**)&Lv, g_lo);
    cudaGetSymbolAddress((void**)&Qhp, g_Qh);
    cudaGetSymbolAddress((void**)&Qlp, g_Ql);
    cudaGetSymbolAddress((void**)&Khp, g_Kh);
    cudaGetSymbolAddress((void**)&Klp, g_Kl);

    cudaFuncSetAttribute(gemm_b3, cudaFuncAttributeMaxDynamicSharedMemorySize, GSM_BYTES);
    cudaFuncSetAttribute(attn_mma, cudaFuncAttributeMaxDynamicSharedMemorySize, SMEM_ATTN);

    const int MQ = NH * DHD;    // 2048
    const int MKV = NKV * DHD;  // 1024

    CvtArgs ca;
    const float* srcs[10] = { pg, ex, Wq0, Wk0, Wv0, Wo0, Wq1, Wk1, Wv1, Wo1 };
    const uint32_t offs[10] = { OP_PG, OP_EX, OP_WQ0, OP_WK0, OP_WV0,
                                OP_WO0, OP_WQ1, OP_WK1, OP_WV1, OP_WO1 };
    const int ns[10] = { BB * L1C * DPG, BB * L2C * DEX, MQ * DPG, MKV * DPG,
                         MKV * DPG, DPG * MQ, MQ * DEX, MKV * DEX, MKV * DEX, DEX * MQ };
    int maxg = 0;
    for (int i = 0; i < 10; i++) {
        ca.src[i] = srcs[i]; ca.off[i] = offs[i]; ca.n16[i] = ns[i] / 16;
        if (ca.n16[i] > maxg) maxg = ca.n16[i];
    }
    cvt_bsplit<<<dim3((maxg + 255) / 256, 10), 256>>>(ca);

    {
        GemmJob j0 = { Hv + OP_PG, Lv + OP_PG, Hv + OP_WQ0, Lv + OP_WQ0,
                       DPG / 2, BB * L1C, 0, 0, L1C, LT, 0,
                       MQ, MQ + MKV, Qd, Kd, Vd, MQ, MKV, MKV, 32, 32 };
        GemmJob j1 = { Hv + OP_EX, Lv + OP_EX, Hv + OP_WQ1, Lv + OP_WQ1,
                       DEX / 2, BB * L2C, 0, 0, L2C, LT, L1C,
                       MQ, MQ + MKV, Qd, Kd, Vd, MQ, MKV, MKV, 32, 16 };
        gemm_b3<<<dim3(32, 32, 2), 128, GSM_BYTES>>>(j0, j1);
    }

    rope_pack2<<<dim3(NH + NKV, LT, BB), 64>>>(Qd, Kd, cs, sn, Qhp, Qlp, Khp, Klp);
    vt_pack<<<dim3(LT / 64, DHD / 64, BB * NKV), 256>>>();

    attn_mma<<<dim3(LT / 64, NH, BB), 256, SMEM_ATTN>>>(mask);

    {
        float* out1 = out + (size_t)BB * L1C * DPG;
        GemmJob j0 = { Ahd, Ald, Hv + OP_WO0, Lv + OP_WO0,
                       MQ / 2, L1C, LT, 0, BB * L1C, 0, 0,
                       DPG, DPG, out, out, out, DPG, DPG, DPG, 18, 32 };
        GemmJob j1 = { Ahd, Ald, Hv + OP_WO1, Lv + OP_WO1,
                       MQ / 2, L2C, LT, L1C, BB * L2C, 0, 0,
                       DEX, DEX, out1, out1, out1, DEX, DEX, DEX, 8, 16 };
        gemm_b3<<<dim3(18, 32, 2), 128, GSM_BYTES>>>(j0, j1);
    }
}

// round 16
// speedup vs baseline: 1.0158x; 1.0158x over previous
#include <cuda_runtime.h>
#include <cuda_bf16.h>
#include <math.h>
#include <stdint.h>

#define BB   4
#define L1C  1024
#define L2C  512
#define LT   1536
#define DPG  2304
#define DEX  1024
#define NH   8
#define NKV  4
#define DHD  256
#define QK_SCALE 0.0625f

#define PERM8(j) ((((j) & 3) << 1) | ((j) >> 2))

// ---------------- scratch (device globals) -----------------------------------
__device__ float g_Q[(size_t)BB * LT * NH * DHD];
__device__ float g_K[(size_t)BB * LT * NKV * DHD];
__device__ float g_V[(size_t)BB * LT * NKV * DHD];

__device__ uint32_t g_Qh[(size_t)BB * LT * NH * 128];
__device__ uint32_t g_Ql[(size_t)BB * LT * NH * 128];
__device__ uint32_t g_Kh[(size_t)BB * LT * NKV * 128];
__device__ uint32_t g_Kl[(size_t)BB * LT * NKV * 128];

__device__ uint32_t g_VTh[(size_t)BB * NKV * DHD * (LT / 2)];
__device__ uint32_t g_VTl[(size_t)BB * NKV * DHD * (LT / 2)];

__device__ uint32_t g_ahi[(size_t)BB * LT * NH * 128];
__device__ uint32_t g_alo[(size_t)BB * LT * NH * 128];

#define OP_PG   0u
#define OP_EX   4718592u
#define OP_WQ0  5767168u
#define OP_WK0  8126464u
#define OP_WV0  9306112u
#define OP_WO0  10485760u
#define OP_WQ1  12845056u
#define OP_WK1  13893632u
#define OP_WV1  14417920u
#define OP_WO1  14942208u
#define OP_TOT  15990784u
__device__ uint32_t g_hi[OP_TOT];
__device__ uint32_t g_lo[OP_TOT];

// ---------------- helpers ----------------------------------------------------
__device__ __forceinline__ uint32_t pack_bf(float a, float b)
{
    __nv_bfloat162 t = __floats2bfloat162_rn(a, b);
    return *(uint32_t*)&t;
}
__device__ __forceinline__ void cpa16(uint32_t dst, const void* src)
{
    asm volatile("cp.async.cg.shared.global [%0], [%1], 16;" :: "r"(dst), "l"(src));
}

#define MMA_BF16(d, a, b)                                                     \
    asm volatile("mma.sync.aligned.m16n8k16.row.col.f32.bf16.bf16.f32 "       \
                 "{%0,%1,%2,%3}, {%4,%5,%6,%7}, {%8,%9}, {%0,%1,%2,%3};"      \
                 : "+f"(d[0]), "+f"(d[1]), "+f"(d[2]), "+f"(d[3])             \
                 : "r"(a[0]), "r"(a[1]), "r"(a[2]), "r"(a[3]),                \
                   "r"(b[0]), "r"(b[1]))

// ---------------- fused bf16-split conversion --------------------------------
struct CvtArgs {
    const float* src[10];
    uint32_t off[10];
    int n16[10];
};

__global__ void cvt_bsplit(CvtArgs a)
{
    const int e = blockIdx.y;
    const int i = blockIdx.x * blockDim.x + threadIdx.x;
    if (i >= a.n16[e]) return;
    const float4* s = (const float4*)(a.src[e]) + (size_t)i * 4;
    uint32_t* hb = g_hi + a.off[e] + (size_t)i * 8;
    uint32_t* lb = g_lo + a.off[e] + (size_t)i * 8;
    float v[16];
#pragma unroll
    for (int q = 0; q < 4; q++) {
        float4 f = s[q];
        v[q * 4 + 0] = f.x; v[q * 4 + 1] = f.y; v[q * 4 + 2] = f.z; v[q * 4 + 3] = f.w;
    }
#pragma unroll
    for (int j = 0; j < 8; j++) {
        const float x0 = v[2 * j], x1 = v[2 * j + 1];
        const float h0 = __bfloat162float(__float2bfloat16_rn(x0));
        const float h1 = __bfloat162float(__float2bfloat16_rn(x1));
        const int p = PERM8(j);
        hb[p] = pack_bf(h0, h1);
        lb[p] = pack_bf(x0 - h0, x1 - h1);
    }
}

// ---------------- bf16x3 NT GEMM: 4 warps, 64x64 warp tile -------------------
#define CH 16
#define PLN (128 * CH)
#define STG (4 * PLN)
#define GSM_BYTES (3 * STG * 4)

struct GemmJob {
    const uint32_t *Ah, *Al, *Wh, *Wl;
    int K2;
    int a_rpb, a_bs, a_off;
    int c_rpb, c_bs, c_off;
    int n1, n2;
    float *C0, *C1, *C2;
    int ldc0, ldc1, ldc2;
    int gx, gy;
};

__global__ __launch_bounds__(128, 2) void gemm_b3(GemmJob j0, GemmJob j1)
{
    const GemmJob J = blockIdx.z ? j1 : j0;
    if ((int)blockIdx.x >= J.gx || (int)blockIdx.y >= J.gy) return;

    extern __shared__ uint32_t smg[];
    const int tid = threadIdx.x;
    const int wid = tid >> 5, lane = tid & 31;
    const int warp_m = wid >> 1, warp_n = wid & 1;
    const int bm = blockIdx.y * 128, bn = blockIdx.x * 128;
    const int K2 = J.K2;

    const int p  = tid >> 5;
    const int tr = tid & 31;
    const uint32_t* pb = (p == 0) ? J.Ah : (p == 1) ? J.Al : (p == 2) ? J.Wh : J.Wl;
    const uint32_t sbase = (uint32_t)__cvta_generic_to_shared(smg);
    const uint32_t* srow[4];
    uint32_t dbase[4];
    int rsw[4];
#pragma unroll
    for (int i = 0; i < 4; i++) {
        const int r = tr * 4 + i;
        int g;
        if (p < 2) {
            const int m = bm + r;
            g = (m / J.a_rpb) * J.a_bs + J.a_off + (m % J.a_rpb);
        } else g = bn + r;
        srow[i] = pb + (size_t)g * K2;
        dbase[i] = sbase + (p * PLN + r * CH) * 4;
        rsw[i]  = (r & 2) << 1;
    }

    float acc[4][8][4];
#pragma unroll
    for (int i = 0; i < 4; i++)
#pragma unroll
        for (int j = 0; j < 8; j++)
#pragma unroll
            for (int r = 0; r < 4; r++) acc[i][j][r] = 0.f;

    const int nk = K2 >> 4;

#define G_ISSUE(kc)                                                           \
    do {                                                                      \
        const int _ko = (kc) * CH;                                            \
        const uint32_t _sb = ((kc) % 3) * STG * 4;                            \
        _Pragma("unroll")                                                     \
        for (int i = 0; i < 4; i++) {                                         \
            _Pragma("unroll")                                                 \
            for (int j = 0; j < 4; j++)                                       \
                cpa16(dbase[i] + _sb + (((2 * j) ^ rsw[i]) * 2) * 4,          \
                      srow[i] + _ko + j * 4);                                 \
        }                                                                     \
        asm volatile("cp.async.commit_group;");                               \
    } while (0)

    G_ISSUE(0);
    G_ISSUE(1);

    const int lr = lane >> 2, lc = lane & 3;
    const int fsw = (lr & 2) << 1;

    for (int kc = 0; kc < nk; kc++) {
        if (kc + 2 < nk) { asm volatile("cp.async.wait_group 1;"); }
        else             { asm volatile("cp.async.wait_group 0;"); }
        __syncthreads();
        if (kc + 2 < nk) G_ISSUE(kc + 2);

        const uint32_t* st = smg + (kc % 3) * STG;
        const uint32_t* ah_p = st + 0 * PLN + (warp_m * 64 + lr) * CH;
        const uint32_t* al_p = st + 1 * PLN + (warp_m * 64 + lr) * CH;
        const uint32_t* wh_p = st + 2 * PLN + (warp_n * 64 + lr) * CH;
        const uint32_t* wl_p = st + 3 * PLN + (warp_n * 64 + lr) * CH;

#pragma unroll
        for (int g = 0; g < 2; g++) {
            const int q2 = ((g * 4 + lc) ^ fsw) * 2;
            uint32_t ah[4][4], bh[8][2];
            uint2 t;
#pragma unroll
            for (int mf = 0; mf < 4; mf++) {
                t = *(const uint2*)(ah_p + mf * 16 * CH + q2);            ah[mf][0] = t.x; ah[mf][2] = t.y;
                t = *(const uint2*)(ah_p + mf * 16 * CH + 8 * CH + q2);   ah[mf][1] = t.x; ah[mf][3] = t.y;
            }
#pragma unroll
            for (int nf = 0; nf < 8; nf++) {
                t = *(const uint2*)(wh_p + nf * 8 * CH + q2);  bh[nf][0] = t.x; bh[nf][1] = t.y;
            }
#pragma unroll
            for (int nf = 0; nf < 8; nf++)
#pragma unroll
                for (int mf = 0; mf < 4; mf++)
                    MMA_BF16(acc[mf][nf], ah[mf], bh[nf]);
#pragma unroll
            for (int mf = 0; mf < 4; mf++) {
                uint32_t al[4];
                t = *(const uint2*)(al_p + mf * 16 * CH + q2);            al[0] = t.x; al[2] = t.y;
                t = *(const uint2*)(al_p + mf * 16 * CH + 8 * CH + q2);   al[1] = t.x; al[3] = t.y;
#pragma unroll
                for (int nf = 0; nf < 8; nf++)
                    MMA_BF16(acc[mf][nf], al, bh[nf]);
            }
#pragma unroll
            for (int nf = 0; nf < 8; nf++) {
                uint32_t bl[2];
                t = *(const uint2*)(wl_p + nf * 8 * CH + q2);  bl[0] = t.x; bl[1] = t.y;
#pragma unroll
                for (int mf = 0; mf < 4; mf++)
                    MMA_BF16(acc[mf][nf], ah[mf], bl);
            }
        }
    }
#undef G_ISSUE

    float* Cb; int ldc, coff;
    if (bn < J.n1)      { Cb = J.C0; ldc = J.ldc0; coff = 0;    }
    else if (bn < J.n2) { Cb = J.C1; ldc = J.ldc1; coff = J.n1; }
    else                { Cb = J.C2; ldc = J.ldc2; coff = J.n2; }

#pragma unroll
    for (int mf = 0; mf < 4; mf++) {
        const int m0 = bm + warp_m * 64 + mf * 16 + lr;
        const int m1 = m0 + 8;
        const int cr0 = (m0 / J.c_rpb) * J.c_bs + J.c_off + (m0 % J.c_rpb);
        const int cr1 = (m1 / J.c_rpb) * J.c_bs + J.c_off + (m1 % J.c_rpb);
#pragma unroll
        for (int nf = 0; nf < 8; nf++) {
            const int col = bn - coff + warp_n * 64 + nf * 8 + lc * 2;
            *(float2*)&Cb[(size_t)cr0 * ldc + col] = make_float2(acc[mf][nf][0], acc[mf][nf][1]);
            *(float2*)&Cb[(size_t)cr1 * ldc + col] = make_float2(acc[mf][nf][2], acc[mf][nf][3]);
        }
    }
}

// ---------------- RoPE + bf16 split + pack (Q and K fused) -------------------
__global__ void rope_pack2(const float* __restrict__ Xq, const float* __restrict__ Xk,
                           const float* __restrict__ cs, const float* __restrict__ sn,
                           uint32_t* __restrict__ qh_, uint32_t* __restrict__ ql_,
                           uint32_t* __restrict__ kh_, uint32_t* __restrict__ kl_)
{
    const int hh = blockIdx.x;
    const int l = blockIdx.y;
    const int b = blockIdx.z;
    const int j = threadIdx.x;
    const int isQ = hh < NH;
    const int h = isQ ? hh : hh - NH;
    const int nheads = isQ ? NH : NKV;
    const float scale = isQ ? QK_SCALE : 1.0f;
    const float* X = isQ ? Xq : Xk;
    uint32_t* oh = isQ ? qh_ : kh_;
    uint32_t* ol = isQ ? ql_ : kl_;

    const size_t row = (size_t)b * LT + l;
    const float2 c2 = *(const float2*)&cs[row * 128 + 2 * j];
    const float2 s2 = *(const float2*)&sn[row * 128 + 2 * j];
    const size_t base = (row * nheads + h) * DHD;
    const float2 xa = *(const float2*)&X[base + 2 * j];
    const float2 xb = *(const float2*)&X[base + 128 + 2 * j];
    const float y1a = (xa.x * c2.x - xb.x * s2.x) * scale;
    const float y1b = (xa.y * c2.y - xb.y * s2.y) * scale;
    const float y2a = (xb.x * c2.x + xa.x * s2.x) * scale;
    const float y2b = (xb.y * c2.y + xa.y * s2.y) * scale;

    const size_t ob = (row * nheads + h) * 128;
    const int p1 = (j & ~7) | PERM8(j & 7);
    const int p2 = 64 + p1;
    const float h1a = __bfloat162float(__float2bfloat16_rn(y1a));
    const float h1b = __bfloat162float(__float2bfloat16_rn(y1b));
    const float h2a = __bfloat162float(__float2bfloat16_rn(y2a));
    const float h2b = __bfloat162float(__float2bfloat16_rn(y2b));
    oh[ob + p1] = pack_bf(h1a, h1b);
    ol[ob + p1] = pack_bf(y1a - h1a, y1b - h1b);
    oh[ob + p2] = pack_bf(h2a, h2b);
    ol[ob + p2] = pack_bf(y2a - h2a, y2b - h2b);
}

// ---------------- V transpose + bf16 split (512 threads, coalesced) ----------
__global__ __launch_bounds__(512) void vt_pack()
{
    __shared__ float t[64][65];
    const int b   = blockIdx.z >> 2;
    const int hkv = blockIdx.z & 3;
    const int l0 = blockIdx.x * 64;
    const int d0 = blockIdx.y * 64;
    const int tid = threadIdx.x;

    for (int i = tid; i < 64 * 64; i += 512) {
        const int lrow = i >> 6, dcol = i & 63;
        t[lrow][dcol] = g_V[(((size_t)b * LT + l0 + lrow) * NKV + hkv) * DHD + d0 + dcol];
    }
    __syncthreads();

    // 8 threads per d-row, 4 pairs each -> 128B-contiguous writes per 8 lanes
    const int drow = tid >> 3;
    const int mg = tid & 7;
    const size_t obase = (((size_t)b * NKV + hkv) * DHD + d0 + drow) * (LT / 2) + l0 / 2;
#pragma unroll
    for (int m = 0; m < 4; m++) {
        const int lp = mg * 4 + m;
        const float v0 = t[2 * lp][drow];
        const float v1 = t[2 * lp + 1][drow];
        const float h0 = __bfloat162float(__float2bfloat16_rn(v0));
        const float h1 = __bfloat162float(__float2bfloat16_rn(v1));
        const int pos = (lp & ~7) | PERM8(lp & 7);
        g_VTh[obase + pos] = pack_bf(h0, h1);
        g_VTl[obase + pos] = pack_bf(v0 - h0, v1 - h1);
    }
}

// ---------------- bf16x3 flash attention, 512 threads ------------------------
#define AQH 0
#define AQL 8192
#define AKH 16384
#define AKL 24576
#define AVH 32768
#define AVL 40960
#define ASF 49152
#define APH 53504
#define APL 55552
#define AAS 57600
#define ALS 57664
#define SMEM_ATTN (57728 * 4)

__global__ __launch_bounds__(512, 1) void attn_mma(const float* __restrict__ mask)
{
    extern __shared__ uint32_t su[];
    float* S   = (float*)(su + ASF);
    float* Asc = (float*)(su + AAS);
    float* Lsc = (float*)(su + ALS);

    const int tid = threadIdx.x;
    const int qt = blockIdx.x;
    const int h  = blockIdx.y;
    const int b  = blockIdx.z;
    const int hkv = h >> 1;
    const int wid = tid >> 5, lane = tid & 31;
    const int wm = wid & 3, wn = wid >> 2;
    const int lr = lane >> 2, lc = lane & 3;
    const int srow = tid >> 3, part = tid & 7;

    const uint32_t sb = (uint32_t)__cvta_generic_to_shared(su);

    {
        const uint32_t* qsrc[2] = { g_Qh, g_Ql };
        const uint32_t* ksrc[2] = { g_Kh, g_Kl };
#pragma unroll
        for (int pl = 0; pl < 2; pl++) {
            for (int i = tid; i < 2048; i += 512) {
                const int row = i >> 5, ch = i & 31;
                const uint32_t dst = sb + ((pl ? AQL : AQH) + row * 128 +
                                           (((2 * ch) ^ ((row & 3) << 2)) * 2)) * 4;
                cpa16(dst, qsrc[pl] + (((size_t)b * LT + qt * 64 + row) * NH + h) * 128 + ch * 4);
            }
            for (int i = tid; i < 2048; i += 512) {
                const int row = i >> 5, ch = i & 31;
                const uint32_t dst = sb + ((pl ? AKL : AKH) + row * 128 +
                                           (((2 * ch) ^ ((row & 3) << 2)) * 2)) * 4;
                cpa16(dst, ksrc[pl] + (((size_t)b * LT + row) * NKV + hkv) * 128 + ch * 4);
            }
        }
        asm volatile("cp.async.commit_group;");
        const uint32_t* vsrc[2] = { g_VTh, g_VTl };
#pragma unroll
        for (int pl = 0; pl < 2; pl++)
            for (int i = tid; i < 2048; i += 512) {
                const int row = i >> 3, ch = i & 7;
                const uint32_t dst = sb + ((pl ? AVL : AVH) + row * 32 +
                                           (((2 * ch) ^ ((row & 3) << 2)) * 2)) * 4;
                cpa16(dst, vsrc[pl] + (((size_t)b * NKV + hkv) * DHD + row) * (LT / 2) + ch * 4);
            }
        asm volatile("cp.async.commit_group;");
    }

    float accO[8][4];
#pragma unroll
    for (int i = 0; i < 8; i++)
#pragma unroll
        for (int j = 0; j < 4; j++) accO[i][j] = 0.f;
    float m_run = -1e30f, l_run = 0.f;

    const int fsw = (lr & 3) << 2;

    for (int kt = 0; kt < LT / 64; kt++) {
        asm volatile("cp.async.wait_group 1;");
        __syncthreads();

        float2 mk0[2], mk1[2];
        {
            const size_t mrow0 = ((size_t)b * LT + qt * 64 + wm * 16 + lr) * LT + kt * 64 + wn * 16;
            const size_t mrow1 = mrow0 + (size_t)8 * LT;
#pragma unroll
            for (int nf = 0; nf < 2; nf++) {
                const int col = nf * 8 + lc * 2;
                mk0[nf] = *(const float2*)&mask[mrow0 + col];
                mk1[nf] = *(const float2*)&mask[mrow1 + col];
            }
        }

        float accS[2][4];
#pragma unroll
        for (int i = 0; i < 2; i++)
#pragma unroll
            for (int j = 0; j < 4; j++) accS[i][j] = 0.f;
        {
            const uint32_t* qh = su + AQH + (wm * 16 + lr) * 128;
            const uint32_t* ql = su + AQL + (wm * 16 + lr) * 128;
            const uint32_t* kh = su + AKH + (wn * 16 + lr) * 128;
            const uint32_t* kl = su + AKL + (wn * 16 + lr) * 128;
#pragma unroll 4
            for (int g = 0; g < 16; g++) {
                const int q2 = ((g * 4 + lc) ^ fsw) * 2;
                uint32_t ah[4], bh[2][2];
                uint2 t;
                t = *(const uint2*)(qh + q2);             ah[0] = t.x; ah[2] = t.y;
                t = *(const uint2*)(qh + 8 * 128 + q2);   ah[1] = t.x; ah[3] = t.y;
#pragma unroll
                for (int nf = 0; nf < 2; nf++) {
                    t = *(const uint2*)(kh + nf * 8 * 128 + q2);  bh[nf][0] = t.x; bh[nf][1] = t.y;
                }
#pragma unroll
                for (int nf = 0; nf < 2; nf++) MMA_BF16(accS[nf], ah, bh[nf]);
                uint32_t al[4];
                t = *(const uint2*)(ql + q2);             al[0] = t.x; al[2] = t.y;
                t = *(const uint2*)(ql + 8 * 128 + q2);   al[1] = t.x; al[3] = t.y;
#pragma unroll
                for (int nf = 0; nf < 2; nf++) {
                    uint32_t bl[2];
                    t = *(const uint2*)(kl + nf * 8 * 128 + q2);  bl[0] = t.x; bl[1] = t.y;
                    MMA_BF16(accS[nf], al, bh[nf]);
                    MMA_BF16(accS[nf], ah, bl);
                }
            }
        }
        {
#pragma unroll
            for (int nf = 0; nf < 2; nf++) {
                const int col = nf * 8 + lc * 2;
                *(float2*)&S[(wm * 16 + lr) * 68 + wn * 16 + col] =
                    make_float2(accS[nf][0] + mk0[nf].x, accS[nf][1] + mk0[nf].y);
                *(float2*)&S[(wm * 16 + lr + 8) * 68 + wn * 16 + col] =
                    make_float2(accS[nf][2] + mk1[nf].x, accS[nf][3] + mk1[nf].y);
            }
        }
        __syncthreads();

        if (kt + 1 < LT / 64) {
            const uint32_t* ksrc[2] = { g_Kh, g_Kl };
#pragma unroll
            for (int pl = 0; pl < 2; pl++)
                for (int i = tid; i < 2048; i += 512) {
                    const int row = i >> 5, ch = i & 31;
                    const uint32_t dst = sb + ((pl ? AKL : AKH) + row * 128 +
                                               (((2 * ch) ^ ((row & 3) << 2)) * 2)) * 4;
                    cpa16(dst, ksrc[pl] + (((size_t)b * LT + (kt + 1) * 64 + row) * NKV + hkv) * 128 + ch * 4);
                }
            asm volatile("cp.async.commit_group;");
        }

        {
            float* sp = S + srow * 68 + part * 8;
            float pv[8];
            float lm = -1e30f;
#pragma unroll
            for (int j = 0; j < 8; j++) { pv[j] = sp[j]; lm = fmaxf(lm, pv[j]); }
            lm = fmaxf(lm, __shfl_xor_sync(0xffffffffu, lm, 1));
            lm = fmaxf(lm, __shfl_xor_sync(0xffffffffu, lm, 2));
            lm = fmaxf(lm, __shfl_xor_sync(0xffffffffu, lm, 4));
            const float mnew = fmaxf(m_run, lm);
            const float alpha = __expf(m_run - mnew);
            float ls = 0.f;
#pragma unroll
            for (int j = 0; j < 8; j++) { pv[j] = __expf(pv[j] - mnew); ls += pv[j]; }
            ls += __shfl_xor_sync(0xffffffffu, ls, 1);
            ls += __shfl_xor_sync(0xffffffffu, ls, 2);
            ls += __shfl_xor_sync(0xffffffffu, ls, 4);
            l_run = l_run * alpha + ls;
            m_run = mnew;
            if (part == 0) Asc[srow] = alpha;

            const int swz = (srow & 3) << 2;
#pragma unroll
            for (int m = 0; m < 4; m++) {
                const float p0 = pv[2 * m], p1 = pv[2 * m + 1];
                const float h0 = __bfloat162float(__float2bfloat16_rn(p0));
                const float h1 = __bfloat162float(__float2bfloat16_rn(p1));
                const int pp = part * 4 + m;
                const int u = (pp & ~7) | PERM8(pp & 7);
                const int pos = srow * 32 + (((u >> 1) ^ swz) * 2) + (u & 1);
                su[APH + pos] = pack_bf(h0, h1);
                su[APL + pos] = pack_bf(p0 - h0, p1 - h1);
            }
        }
        if (kt + 1 < LT / 64) { asm volatile("cp.async.wait_group 1;"); }
        else                  { asm volatile("cp.async.wait_group 0;"); }
        __syncthreads();

        {
            const float a0 = Asc[wm * 16 + lr];
            const float a1 = Asc[wm * 16 + lr + 8];
#pragma unroll
            for (int nf = 0; nf < 8; nf++) {
                accO[nf][0] *= a0; accO[nf][1] *= a0;
                accO[nf][2] *= a1; accO[nf][3] *= a1;
            }
            const uint32_t* php = su + APH + (wm * 16 + lr) * 32;
            const uint32_t* plp = su + APL + (wm * 16 + lr) * 32;
            const uint32_t* vhp = su + AVH + (wn * 64 + lr) * 32;
            const uint32_t* vlp = su + AVL + (wn * 64 + lr) * 32;
#pragma unroll
            for (int g = 0; g < 4; g++) {
                const int q2 = ((g * 4 + lc) ^ fsw) * 2;
                uint32_t ph[4], vh[8][2];
                uint2 t;
                t = *(const uint2*)(php + q2);            ph[0] = t.x; ph[2] = t.y;
                t = *(const uint2*)(php + 8 * 32 + q2);   ph[1] = t.x; ph[3] = t.y;
#pragma unroll
                for (int nf = 0; nf < 8; nf++) {
                    t = *(const uint2*)(vhp + nf * 8 * 32 + q2);  vh[nf][0] = t.x; vh[nf][1] = t.y;
                }
#pragma unroll
                for (int nf = 0; nf < 8; nf++) MMA_BF16(accO[nf], ph, vh[nf]);
                uint32_t pl[4];
                t = *(const uint2*)(plp + q2);            pl[0] = t.x; pl[2] = t.y;
                t = *(const uint2*)(plp + 8 * 32 + q2);   pl[1] = t.x; pl[3] = t.y;
#pragma unroll
                for (int nf = 0; nf < 8; nf++) {
                    uint32_t vl[2];
                    t = *(const uint2*)(vlp + nf * 8 * 32 + q2);  vl[0] = t.x; vl[1] = t.y;
                    MMA_BF16(accO[nf], pl, vh[nf]);
                    MMA_BF16(accO[nf], ph, vl);
                }
            }
        }
        __syncthreads();

        if (kt + 1 < LT / 64) {
            const uint32_t* vsrc[2] = { g_VTh, g_VTl };
#pragma unroll
            for (int pl = 0; pl < 2; pl++)
                for (int i = tid; i < 2048; i += 512) {
                    const int row = i >> 3, ch = i & 7;
                    const uint32_t dst = sb + ((pl ? AVL : AVH) + row * 32 +
                                               (((2 * ch) ^ ((row & 3) << 2)) * 2)) * 4;
                    cpa16(dst, vsrc[pl] + (((size_t)b * NKV + hkv) * DHD + row) * (LT / 2) +
                               (kt + 1) * 32 + ch * 4);
                }
            asm volatile("cp.async.commit_group;");
        }
    }

    if (part == 0) Lsc[srow] = l_run;
    __syncthreads();

    {
        const float il0 = 1.f / Lsc[wm * 16 + lr];
        const float il1 = 1.f / Lsc[wm * 16 + lr + 8];
        const size_t r0 = (size_t)b * LT + qt * 64 + wm * 16 + lr;
        const size_t r1 = r0 + 8;
#pragma unroll
        for (int nf = 0; nf < 8; nf++) {
            const int p = h * 128 + wn * 32 + nf * 4 + lc;
            const int pos = (p & ~7) | PERM8(p & 7);
            const float v0 = accO[nf][0] * il0, v1 = accO[nf][1] * il0;
            const float v2 = accO[nf][2] * il1, v3 = accO[nf][3] * il1;
            const float h0 = __bfloat162float(__float2bfloat16_rn(v0));
            const float h1 = __bfloat162float(__float2bfloat16_rn(v1));
            const float h2 = __bfloat162float(__float2bfloat16_rn(v2));
            const float h3 = __bfloat162float(__float2bfloat16_rn(v3));
            g_ahi[r0 * 1024 + pos] = pack_bf(h0, h1);
            g_alo[r0 * 1024 + pos] = pack_bf(v0 - h0, v1 - h1);
            g_ahi[r1 * 1024 + pos] = pack_bf(h2, h3);
            g_alo[r1 * 1024 + pos] = pack_bf(v2 - h2, v3 - h3);
        }
    }
}

// ---------------- launch ----------------------------------------------------
extern "C" void kernel_launch(void* const* d_in, const int* in_sizes, int n_in,
                              void* d_out, int out_size)
{
    const float* pg   = (const float*)d_in[0];
    const float* ex   = (const float*)d_in[1];
    const float* cs   = (const float*)d_in[2];
    const float* sn   = (const float*)d_in[3];
    const float* mask = (const float*)d_in[4];
    const float* Wq0  = (const float*)d_in[5];
    const float* Wk0  = (const float*)d_in[6];
    const float* Wv0  = (const float*)d_in[7];
    const float* Wo0  = (const float*)d_in[8];
    const float* Wq1  = (const float*)d_in[9];
    const float* Wk1  = (const float*)d_in[10];
    const float* Wv1  = (const float*)d_in[11];
    const float* Wo1  = (const float*)d_in[12];
    float* out = (float*)d_out;

    float *Qd, *Kd, *Vd;
    uint32_t *Ahd, *Ald, *Hv, *Lv, *Qhp, *Qlp, *Khp, *Klp;
    cudaGetSymbolAddress((void**)&Qd, g_Q);
    cudaGetSymbolAddress((void**)&Kd, g_K);
    cudaGetSymbolAddress((void**)&Vd, g_V);
    cudaGetSymbolAddress((void**)&Ahd, g_ahi);
    cudaGetSymbolAddress((void**)&Ald, g_alo);
    cudaGetSymbolAddress((void**)&Hv, g_hi);
    cudaGetSymbolAddress((void**)&Lv, g_lo);
    cudaGetSymbolAddress((void**)&Qhp, g_Qh);
    cudaGetSymbolAddress((void**)&Qlp, g_Ql);
    cudaGetSymbolAddress((void**)&Khp, g_Kh);
    cudaGetSymbolAddress((void**)&Klp, g_Kl);

    cudaFuncSetAttribute(gemm_b3, cudaFuncAttributeMaxDynamicSharedMemorySize, GSM_BYTES);
    cudaFuncSetAttribute(attn_mma, cudaFuncAttributeMaxDynamicSharedMemorySize, SMEM_ATTN);

    const int MQ = NH * DHD;    // 2048
    const int MKV = NKV * DHD;  // 1024

    CvtArgs ca;
    const float* srcs[10] = { pg, ex, Wq0, Wk0, Wv0, Wo0, Wq1, Wk1, Wv1, Wo1 };
    const uint32_t offs[10] = { OP_PG, OP_EX, OP_WQ0, OP_WK0, OP_WV0,
                                OP_WO0, OP_WQ1, OP_WK1, OP_WV1, OP_WO1 };
    const int ns[10] = { BB * L1C * DPG, BB * L2C * DEX, MQ * DPG, MKV * DPG,
                         MKV * DPG, DPG * MQ, MQ * DEX, MKV * DEX, MKV * DEX, DEX * MQ };
    int maxg = 0;
    for (int i = 0; i < 10; i++) {
        ca.src[i] = srcs[i]; ca.off[i] = offs[i]; ca.n16[i] = ns[i] / 16;
        if (ca.n16[i] > maxg) maxg = ca.n16[i];
    }
    cvt_bsplit<<<dim3((maxg + 255) / 256, 10), 256>>>(ca);

    {
        GemmJob j0 = { Hv + OP_PG, Lv + OP_PG, Hv + OP_WQ0, Lv + OP_WQ0,
                       DPG / 2, BB * L1C, 0, 0, L1C, LT, 0,
                       MQ, MQ + MKV, Qd, Kd, Vd, MQ, MKV, MKV, 32, 32 };
        GemmJob j1 = { Hv + OP_EX, Lv + OP_EX, Hv + OP_WQ1, Lv + OP_WQ1,
                       DEX / 2, BB * L2C, 0, 0, L2C, LT, L1C,
                       MQ, MQ + MKV, Qd, Kd, Vd, MQ, MKV, MKV, 32, 16 };
        gemm_b3<<<dim3(32, 32, 2), 128, GSM_BYTES>>>(j0, j1);
    }

    rope_pack2<<<dim3(NH + NKV, LT, BB), 64>>>(Qd, Kd, cs, sn, Qhp, Qlp, Khp, Klp);
    vt_pack<<<dim3(LT / 64, DHD / 64, BB * NKV), 512>>>();

    attn_mma<<<dim3(LT / 64, NH, BB), 512, SMEM_ATTN>>>(mask);

    {
        float* out1 = out + (size_t)BB * L1C * DPG;
        GemmJob j0 = { Ahd, Ald, Hv + OP_WO0, Lv + OP_WO0,
                       MQ / 2, L1C, LT, 0, BB * L1C, 0, 0,
                       DPG, DPG, out, out, out, DPG, DPG, DPG, 18, 32 };
        GemmJob j1 = { Ahd, Ald, Hv + OP_WO1, Lv + OP_WO1,
                       MQ / 2, L2C, LT, L1C, BB * L2C, 0, 0,
                       DEX, DEX, out1, out1, out1, DEX, DEX, DEX, 8, 16 };
        gemm_b3<<<dim3(18, 32, 2), 128, GSM_BYTES>>>(j0, j1);
    }
}